// round 16
// baseline (speedup 1.0000x reference)
#include <cuda_runtime.h>
#include <cuda_fp16.h>
#include <cstdint>
#include <cstddef>

#define BB   2048
#define TT   128
#define FF   64
#define HH   256
#define OL   32
#define FCH  256
#define BM   16
#define ASP  10

// ---- device scratch ----
__device__ __half g_hsh[(size_t)TT * BB * HH];      // [t][b][j] fp16
__device__ unsigned g_gi[(size_t)TT * 3 * 256 * 1024]; // x-part gates, fp16 pairs (201MB)
__device__ uint2    g_W4h[160 * 256];               // enc fp16 weights (4 of 6)
__device__ unsigned g_W2h[160 * 256];               // enc fp16 weights (2 of 6)
__device__ float4 g_D6a[128 * 256];
__device__ float2 g_D6b[128 * 256];
__device__ float2 g_F2 [128 * 256];
__device__ float  g_brz[512], g_bin[256], g_bhn[256];
__device__ float  g_dbrz[512], g_dbin[256], g_dbhn[256];
__device__ float  g_Abt[(size_t)BB * TT];
__device__ float  g_Cbt[(size_t)BB * TT];
__device__ float  g_prev[BB];

typedef unsigned long long u64;

__device__ __forceinline__ void fma2(u64 &d, u64 a, u64 b) {
    asm("fma.rn.f32x2 %0, %1, %2, %0;" : "+l"(d) : "l"(a), "l"(b));
}
__device__ __forceinline__ u64 pack2(float w) {
    u64 r; unsigned int u = __float_as_uint(w);
    asm("mov.b64 %0, {%1,%1};" : "=l"(r) : "r"(u));
    return r;
}
__device__ __forceinline__ float2 u2f(u64 v) {
    float2 r;
    asm("mov.b64 {%0, %1}, %2;" : "=f"(r.x), "=f"(r.y) : "l"(v));
    return r;
}
__device__ __forceinline__ u64 hfp(unsigned v) {     // 2 fp16 -> packed f32x2
    __half2 h2 = *reinterpret_cast<__half2*>(&v);
    float2 f = __half22float2(h2);
    u64 r;
    asm("mov.b64 %0, {%1,%2};" : "=l"(r) : "f"(f.x), "f"(f.y));
    return r;
}
__device__ __forceinline__ float2 h2f(unsigned v) {
    __half2 h2 = *reinterpret_cast<__half2*>(&v);
    return __half22float2(h2);
}
__device__ __forceinline__ unsigned f2h2(float a, float b) {
    __half2 h = __floats2half2_rn(a, b);
    return *reinterpret_cast<unsigned*>(&h);
}
__device__ __forceinline__ unsigned u64toh2(u64 v) { // packed f32x2 -> 2 fp16
    float2 f = u2f(v);
    return f2h2(f.x, f.y);
}
__device__ __forceinline__ float sigf(float x) { return 1.f / (1.f + __expf(-x)); }

// ---- prep (R12-proven) ----
__global__ void prep_kernel(const float* __restrict__ x,
                            const float* __restrict__ eWih, const float* __restrict__ eWhh,
                            const float* __restrict__ ebih, const float* __restrict__ ebhh,
                            const float* __restrict__ dWhh,
                            const float* __restrict__ dbih, const float* __restrict__ dbhh,
                            const float* __restrict__ fc1W) {
    const int stride = gridDim.x * blockDim.x;
    const int id = blockIdx.x * blockDim.x + threadIdx.x;
    for (int i = id; i < 160 * 256; i += stride) {
        int q = i >> 8, j = i & 255;
        float wr0, wz0, w30, wr1, wz1, w31;
        if (q < 32) {
            int k0 = 2 * q, k1 = k0 + 1;
            wr0 = eWih[j * 64 + k0];         wr1 = eWih[j * 64 + k1];
            wz0 = eWih[(256 + j) * 64 + k0]; wz1 = eWih[(256 + j) * 64 + k1];
            w30 = eWih[(512 + j) * 64 + k0]; w31 = eWih[(512 + j) * 64 + k1];
        } else {
            int k0 = 2 * q - 64, k1 = k0 + 1;
            wr0 = eWhh[j * 256 + k0];         wr1 = eWhh[j * 256 + k1];
            wz0 = eWhh[(256 + j) * 256 + k0]; wz1 = eWhh[(256 + j) * 256 + k1];
            w30 = eWhh[(512 + j) * 256 + k0]; w31 = eWhh[(512 + j) * 256 + k1];
        }
        g_W4h[i] = make_uint2(f2h2(wr0, wz0), f2h2(w30, wr1));
        g_W2h[i] = f2h2(wz1, w31);
    }
    for (int i = id; i < 128 * 256; i += stride) {
        int q = i >> 8, j = i & 255;
        int k0 = 2 * q, k1 = k0 + 1;
        g_D6a[i] = make_float4(dWhh[j * 256 + k0], dWhh[(256 + j) * 256 + k0],
                               dWhh[(512 + j) * 256 + k0], dWhh[j * 256 + k1]);
        g_D6b[i] = make_float2(dWhh[(256 + j) * 256 + k1], dWhh[(512 + j) * 256 + k1]);
        g_F2[i]  = make_float2(fc1W[j * 256 + k0], fc1W[j * 256 + k1]);
    }
    for (int i = id; i < 512; i += stride) {
        g_brz[i]  = ebih[i] + ebhh[i];
        g_dbrz[i] = dbih[i] + dbhh[i];
    }
    for (int i = id; i < 256; i += stride) {
        g_bin[i]  = ebih[512 + i];  g_bhn[i]  = ebhh[512 + i];
        g_dbin[i] = dbih[512 + i];  g_dbhn[i] = dbhh[512 + i];
    }
    for (int i = id; i < BB; i += stride)
        g_prev[i] = x[((size_t)i * TT + (TT - 1)) * FF];
}

// 2-k fma2 body; wa=uint2 (4 fp16), wb=unsigned (2 fp16); stride ST; gates aR,aZ,A3
#define GRU6(K0, ST, A3) do {                                                              \
    const double2* _a0 = reinterpret_cast<const double2*>(As + (K0) * (ST));               \
    const double2* _a1 = reinterpret_cast<const double2*>(As + ((K0) + 1) * (ST));         \
    float2 _f0 = h2f(wa.x), _f1 = h2f(wa.y), _f2 = h2f(wb);                                \
    u64 _p00 = pack2(_f0.x), _p01 = pack2(_f0.y), _p02 = pack2(_f1.x);                     \
    u64 _p10 = pack2(_f1.y), _p11 = pack2(_f2.x), _p12 = pack2(_f2.y);                     \
    _Pragma("unroll")                                                                      \
    for (int _h = 0; _h < 4; _h++) {                                                       \
        double2 _d0 = _a0[_h], _d1 = _a1[_h];                                              \
        u64 _a00 = __double_as_longlong(_d0.x), _a01 = __double_as_longlong(_d0.y);        \
        u64 _a10 = __double_as_longlong(_d1.x), _a11 = __double_as_longlong(_d1.y);        \
        fma2(aR[2*_h],   _p00, _a00); fma2(aZ[2*_h],   _p01, _a00); fma2(A3[2*_h],   _p02, _a00); \
        fma2(aR[2*_h+1], _p00, _a01); fma2(aZ[2*_h+1], _p01, _a01); fma2(A3[2*_h+1], _p02, _a01); \
        fma2(aR[2*_h],   _p10, _a10); fma2(aZ[2*_h],   _p11, _a10); fma2(A3[2*_h],   _p12, _a10); \
        fma2(aR[2*_h+1], _p10, _a11); fma2(aZ[2*_h+1], _p11, _a11); fma2(A3[2*_h+1], _p12, _a11); \
    }                                                                                      \
} while (0)

// ---- gi precompute: x-part of gates for all t in parallel; fp16-pair output ----
__global__ void __launch_bounds__(256) gi_kernel(const float* __restrict__ x) {
    __shared__ float2 As[64 * 8];
    float* Asf = reinterpret_cast<float*>(As);
    const int tid = threadIdx.x;
    const int B0 = (blockIdx.x & 127) * BM;
    const int T0 = (blockIdx.x >> 7) * 16;
    for (int t = T0; t < T0 + 16; t++) {
        for (int i = tid; i < BM * FF; i += 256) {
            int b = i >> 6, k = i & 63;
            Asf[(k * 8 + (b >> 1)) * 2 + (b & 1)] = x[((size_t)(B0 + b) * TT + t) * FF + k];
        }
        __syncthreads();
        u64 aR[8], aZ[8], aI[8];
#pragma unroll
        for (int p = 0; p < 8; p++) { aR[p] = 0; aZ[p] = 0; aI[p] = 0; }
        for (int q = 0; q < 32; q++) {
            uint2 wa = g_W4h[q * 256 + tid];
            unsigned wb = g_W2h[q * 256 + tid];
            GRU6(2 * q, 8, aI);
        }
        unsigned* dst = g_gi + (((size_t)t * 3) * 256 + tid) * 1024 + (B0 >> 1);
#pragma unroll
        for (int p = 0; p < 8; p++) {
            dst[p] = u64toh2(aR[p]);
            dst[256 * 1024 + p] = u64toh2(aZ[p]);
            dst[512 * 1024 + p] = u64toh2(aI[p]);
        }
        __syncthreads();
    }
}

// ---- persistent encoder: h-part only; gi preloaded; no in-loop attention ----
__global__ void __launch_bounds__(256) enc_all_kernel(const float* __restrict__ h0) {
    __shared__ float2 As[256 * ASP];            // h rows [k][pair]
    float* Asf = reinterpret_cast<float*>(As);
    const int tid = threadIdx.x;
    const int B0 = blockIdx.x * BM;
    for (int i = tid; i < BM * HH; i += 256) {
        int b = i >> 8, k = i & 255;
        Asf[(k * ASP + (b >> 1)) * 2 + (b & 1)] = h0[(size_t)(B0 + b) * HH + k];
    }
    const float brz1 = g_brz[tid], brz2 = g_brz[256 + tid];
    const float bi = g_bin[tid], bh = g_bhn[tid];
    const int offh = (blockIdx.x * 37) & 127;
    __syncthreads();

    int q = 32 + offh;
    uint2    wa = g_W4h[q * 256 + tid];
    unsigned wb = g_W2h[q * 256 + tid];

    for (int t = 0; t < TT; t++) {
        // preload gi (fp16 pairs) for this step
        unsigned giR[8], giZ[8], giI[8];
        {
            const unsigned* src = g_gi + (((size_t)t * 3) * 256 + tid) * 1024 + (B0 >> 1);
#pragma unroll
            for (int p = 0; p < 8; p++) {
                giR[p] = src[p];
                giZ[p] = src[256 * 1024 + p];
                giI[p] = src[512 * 1024 + p];
            }
        }
        u64 aR[8], aZ[8], aH[8];
#pragma unroll
        for (int p = 0; p < 8; p++) { aR[p] = hfp(giR[p]); aZ[p] = hfp(giZ[p]); aH[p] = 0; }

        for (int i = 0; i < 128; i++) {            // h-part: r,z,h_n
            int qn = 32 + ((offh + i + 1) & 127);
            uint2 wan = g_W4h[qn * 256 + tid];
            unsigned wbn = g_W2h[qn * 256 + tid];
            GRU6(2 * (q - 32), ASP, aH);
            wa = wan; wb = wbn; q = qn;
        }
        __syncthreads();   // GEMM reads of As done

        __half* __restrict__ hsh = g_hsh + ((size_t)t * BB + B0) * HH + tid;
#pragma unroll
        for (int p = 0; p < 8; p++) {
            float2 fr = u2f(aR[p]), fz = u2f(aZ[p]), fh = u2f(aH[p]);
            float2 fi = h2f(giI[p]);
            float2 hp = As[tid * ASP + p];
            float r0 = sigf(fr.x + brz1), z0 = sigf(fz.x + brz2);
            float n0 = tanhf(fi.x + bi + r0 * (fh.x + bh));
            float h0n = (1.f - z0) * n0 + z0 * hp.x;
            float r1 = sigf(fr.y + brz1), z1 = sigf(fz.y + brz2);
            float n1 = tanhf(fi.y + bi + r1 * (fh.y + bh));
            float h1n = (1.f - z1) * n1 + z1 * hp.y;
            As[tid * ASP + p] = make_float2(h0n, h1n);
            hsh[(size_t)(2 * p) * HH]     = __float2half_rn(h0n);
            hsh[(size_t)(2 * p + 1) * HH] = __float2half_rn(h1n);
        }
        __syncthreads();   // As updates visible before next GEMM
    }
}

// ---- attention precompute from fp16 hs: A=scale*wq.h, C=scale*bq.h ----
__global__ void __launch_bounds__(256) attn_pre_kernel(const float* __restrict__ wq,
                                                       const float* __restrict__ bq) {
    const int g = blockIdx.x * 8 + (threadIdx.x >> 5);
    const int lane = threadIdx.x & 31;
    const int b = g >> 7, t = g & 127;
    const uint2* hv = reinterpret_cast<const uint2*>(g_hsh + ((size_t)t * BB + b) * HH);
    float a = 0.f, c = 0.f;
#pragma unroll
    for (int r = 0; r < 2; r++) {
        int idx = lane + r * 32;
        uint2 v = hv[idx];
        float2 f0 = h2f(v.x), f1 = h2f(v.y);
        int k = idx * 4;
        a += f0.x * wq[k] + f0.y * wq[k + 1] + f1.x * wq[k + 2] + f1.y * wq[k + 3];
        c += f0.x * bq[k] + f0.y * bq[k + 1] + f1.x * bq[k + 2] + f1.y * bq[k + 3];
    }
#pragma unroll
    for (int o = 16; o > 0; o >>= 1) {
        a += __shfl_xor_sync(0xffffffffu, a, o);
        c += __shfl_xor_sync(0xffffffffu, c, o);
    }
    if (lane == 0) {
        g_Abt[(size_t)b * TT + t] = a * 0.0625f;
        g_Cbt[(size_t)b * TT + t] = c * 0.0625f;
    }
}

#define DEC_STEP6(K0) do {                                                                 \
    const double2* _av0 = reinterpret_cast<const double2*>(ctxp + (K0) * 8);               \
    const double2* _av1 = reinterpret_cast<const double2*>(ctxp + ((K0) + 1) * 8);         \
    u64 _p00 = pack2(wa.x), _p01 = pack2(wa.y), _p02 = pack2(wa.z);                        \
    u64 _p10 = pack2(wa.w), _p11 = pack2(wb.x), _p12 = pack2(wb.y);                        \
    _Pragma("unroll")                                                                      \
    for (int _h = 0; _h < 4; _h++) {                                                       \
        double2 _d0 = _av0[_h], _d1 = _av1[_h];                                            \
        u64 _a00 = __double_as_longlong(_d0.x), _a01 = __double_as_longlong(_d0.y);        \
        u64 _a10 = __double_as_longlong(_d1.x), _a11 = __double_as_longlong(_d1.y);        \
        fma2(ar[2*_h],   _p00, _a00); fma2(az[2*_h],   _p01, _a00); fma2(an[2*_h],   _p02, _a00); \
        fma2(ar[2*_h+1], _p00, _a01); fma2(az[2*_h+1], _p01, _a01); fma2(an[2*_h+1], _p02, _a01); \
        fma2(ar[2*_h],   _p10, _a10); fma2(az[2*_h],   _p11, _a10); fma2(an[2*_h],   _p12, _a10); \
        fma2(ar[2*_h+1], _p10, _a11); fma2(az[2*_h+1], _p11, _a11); fma2(an[2*_h+1], _p12, _a11); \
    }                                                                                      \
} while (0)

// ---- persistent decoder (R12-proven) ----
__global__ void __launch_bounds__(256) dec_all_kernel(const float* __restrict__ dWih,
                                                      const float* __restrict__ fc1b,
                                                      const float* __restrict__ fc2W,
                                                      const float* __restrict__ fc2b,
                                                      float* __restrict__ out) {
    __shared__ char smraw[8192 + 16384 + 16384 + 64];
    float*  s     = reinterpret_cast<float*>(smraw);
    float2* ctxp  = reinterpret_cast<float2*>(smraw + 8192);
    float*  f1s   = reinterpret_cast<float*>(smraw + 8192);
    float2* hdp   = reinterpret_cast<float2*>(smraw + 8192 + 16384);
    float*  prevs = reinterpret_cast<float*>(smraw + 8192 + 32768);
    const int tid = threadIdx.x;
    const int B0 = blockIdx.x * BM;
    const int wid = tid >> 5, lane = tid & 31;
    const int j = tid;
    const int toff = (blockIdx.x * 29) & 127;
    const int qoff = (blockIdx.x * 13) & 127;

    if (tid < BM) prevs[tid] = g_prev[B0 + tid];
    const float dwr = dWih[j], dwz = dWih[256 + j], dwn = dWih[512 + j];
    const float br = g_dbrz[j], bz = g_dbrz[256 + j], bi = g_dbin[j], bh = g_dbhn[j];
    const float b1 = fc1b[tid], fb = fc2b[0];
    float w2r[8];
#pragma unroll
    for (int qq = 0; qq < 8; qq++) w2r[qq] = fc2W[lane + 32 * qq];
    __syncthreads();

    for (int step = 0; step < OL; step++) {
        for (int i = tid; i < BM * TT; i += 256) {
            int b = i >> 7;
            s[i] = prevs[b] * g_Abt[(size_t)B0 * TT + i] + g_Cbt[(size_t)B0 * TT + i];
        }
        __syncthreads();

#pragma unroll
        for (int bb = 0; bb < 2; bb++) {
            int b = wid * 2 + bb;
            float v0 = s[b*TT+lane], v1 = s[b*TT+lane+32], v2 = s[b*TT+lane+64], v3 = s[b*TT+lane+96];
            float m = fmaxf(fmaxf(v0, v1), fmaxf(v2, v3));
#pragma unroll
            for (int o = 16; o > 0; o >>= 1) m = fmaxf(m, __shfl_xor_sync(0xffffffffu, m, o));
            float e0 = __expf(v0-m), e1 = __expf(v1-m), e2 = __expf(v2-m), e3 = __expf(v3-m);
            float sum = e0 + e1 + e2 + e3;
#pragma unroll
            for (int o = 16; o > 0; o >>= 1) sum += __shfl_xor_sync(0xffffffffu, sum, o);
            float inv = 1.f / sum;
            s[b*TT+lane] = e0*inv; s[b*TT+lane+32] = e1*inv; s[b*TT+lane+64] = e2*inv; s[b*TT+lane+96] = e3*inv;
        }
        __syncthreads();

        {   // ctx over fp16 hs
            const int jv = (tid & 63) * 4;
            const int bs = tid >> 6;
            u64 c0[2] = {0,0}, c1[2] = {0,0}, c2[2] = {0,0}, c3[2] = {0,0};
#pragma unroll 4
            for (int i = 0; i < TT; i++) {
                int t = (i + toff) & 127;
                const uint2* hb = reinterpret_cast<const uint2*>(
                    g_hsh + ((size_t)t * BB + B0) * HH) + (jv >> 2);
                float w0 = s[(bs+0)*TT+t], w1 = s[(bs+4)*TT+t], w2 = s[(bs+8)*TT+t], w3 = s[(bs+12)*TT+t];
                uint2 v0 = hb[(bs+0)*64], v1 = hb[(bs+4)*64], v2 = hb[(bs+8)*64], v3 = hb[(bs+12)*64];
                u64 wp0 = pack2(w0), wp1 = pack2(w1), wp2 = pack2(w2), wp3 = pack2(w3);
                fma2(c0[0], wp0, hfp(v0.x)); fma2(c0[1], wp0, hfp(v0.y));
                fma2(c1[0], wp1, hfp(v1.x)); fma2(c1[1], wp1, hfp(v1.y));
                fma2(c2[0], wp2, hfp(v2.x)); fma2(c2[1], wp2, hfp(v2.y));
                fma2(c3[0], wp3, hfp(v3.x)); fma2(c3[1], wp3, hfp(v3.y));
            }
            float* cf = reinterpret_cast<float*>(ctxp);
            u64* cc[4] = {c0, c1, c2, c3};
#pragma unroll
            for (int qq = 0; qq < 4; qq++) {
                int b = bs + 4 * qq, p = b >> 1, par = b & 1;
                float2 lo = u2f(cc[qq][0]), hi = u2f(cc[qq][1]);
                cf[((jv+0)*8+p)*2+par] = lo.x; cf[((jv+1)*8+p)*2+par] = lo.y;
                cf[((jv+2)*8+p)*2+par] = hi.x; cf[((jv+3)*8+p)*2+par] = hi.y;
            }
        }
        __syncthreads();

        u64 ar[8], az[8], an[8];
#pragma unroll
        for (int p = 0; p < 8; p++) { ar[p] = 0; az[p] = 0; an[p] = 0; }
        {
            int q = qoff;
            float4 wa = g_D6a[q * 256 + tid];
            float2 wb = g_D6b[q * 256 + tid];
            for (int i = 0; i < 128; i++) {
                int qn = (qoff + i + 1) & 127;
                float4 wan = g_D6a[qn * 256 + tid];
                float2 wbn = g_D6b[qn * 256 + tid];
                DEC_STEP6(2 * q);
                wa = wan; wb = wbn; q = qn;
            }
        }
        {
#pragma unroll
            for (int p = 0; p < 8; p++) {
                float2 fr = u2f(ar[p]), fz = u2f(az[p]), fn = u2f(an[p]);
                float2 cx = ctxp[j * 8 + p];
                float2 hd;
                float pv = prevs[2 * p];
                float r = sigf(pv * dwr + fr.x + br);
                float z = sigf(pv * dwz + fz.x + bz);
                float n = tanhf(pv * dwn + bi + r * (fn.x + bh));
                hd.x = (1.f - z) * n + z * cx.x;
                pv = prevs[2 * p + 1];
                r = sigf(pv * dwr + fr.y + br);
                z = sigf(pv * dwz + fz.y + bz);
                n = tanhf(pv * dwn + bi + r * (fn.y + bh));
                hd.y = (1.f - z) * n + z * cx.y;
                hdp[j * 8 + p] = hd;
            }
        }
        __syncthreads();

        {
            u64 f[8];
#pragma unroll
            for (int p = 0; p < 8; p++) f[p] = 0;
            int q = qoff;
            float2 wf = g_F2[q * 256 + tid];
            for (int i = 0; i < 128; i++) {
                int qn = (qoff + i + 1) & 127;
                float2 wfn = g_F2[qn * 256 + tid];
                const double2* hv0 = reinterpret_cast<const double2*>(hdp + (2 * q) * 8);
                const double2* hv1 = reinterpret_cast<const double2*>(hdp + (2 * q + 1) * 8);
                u64 w0 = pack2(wf.x), w1 = pack2(wf.y);
#pragma unroll
                for (int h = 0; h < 4; h++) {
                    double2 d0 = hv0[h], d1 = hv1[h];
                    fma2(f[2*h],   w0, __double_as_longlong(d0.x));
                    fma2(f[2*h+1], w0, __double_as_longlong(d0.y));
                    fma2(f[2*h],   w1, __double_as_longlong(d1.x));
                    fma2(f[2*h+1], w1, __double_as_longlong(d1.y));
                }
                wf = wfn; q = qn;
            }
#pragma unroll
            for (int p = 0; p < 8; p++) {
                float2 v = u2f(f[p]);
                f1s[(2*p)*FCH + tid]   = fmaxf(v.x + b1, 0.f);
                f1s[(2*p+1)*FCH + tid] = fmaxf(v.y + b1, 0.f);
            }
        }
        __syncthreads();

        {
#pragma unroll
            for (int bb = 0; bb < 2; bb++) {
                int b = wid * 2 + bb;
                float a = 0.f;
#pragma unroll
                for (int qq = 0; qq < 8; qq++)
                    a += f1s[b * FCH + lane + 32 * qq] * w2r[qq];
#pragma unroll
                for (int o = 16; o > 0; o >>= 1) a += __shfl_xor_sync(0xffffffffu, a, o);
                if (lane == 0) {
                    float v = a + fb;
                    out[(size_t)(B0 + b) * OL + step] = v;
                    prevs[b] = v;
                }
            }
        }
        __syncthreads();
    }
}

extern "C" void kernel_launch(void* const* d_in, const int* in_sizes, int n_in,
                              void* d_out, int out_size) {
    const float* x      = (const float*)d_in[0];
    const float* h      = (const float*)d_in[1];
    const float* eWih   = (const float*)d_in[2];
    const float* eWhh   = (const float*)d_in[3];
    const float* ebih   = (const float*)d_in[4];
    const float* ebhh   = (const float*)d_in[5];
    const float* dWih   = (const float*)d_in[6];
    const float* dWhh   = (const float*)d_in[7];
    const float* dbih   = (const float*)d_in[8];
    const float* dbhh   = (const float*)d_in[9];
    const float* wq     = (const float*)d_in[10];
    const float* bq     = (const float*)d_in[11];
    const float* fc1W   = (const float*)d_in[12];
    const float* fc1b   = (const float*)d_in[13];
    const float* fc2W   = (const float*)d_in[14];
    const float* fc2b   = (const float*)d_in[15];
    float* out = (float*)d_out;

    prep_kernel<<<256, 256>>>(x, eWih, eWhh, ebih, ebhh, dWhh, dbih, dbhh, fc1W);
    gi_kernel<<<1024, 256>>>(x);
    enc_all_kernel<<<BB / BM, 256>>>(h);
    attn_pre_kernel<<<(BB * TT) / 8, 256>>>(wq, bq);
    dec_all_kernel<<<BB / BM, 256>>>(dWih, fc1b, fc2W, fc2b, out);
}